// round 13
// baseline (speedup 1.0000x reference)
#include <cuda_runtime.h>
#include <cstdint>

// MinArchitecture scan, 1 row/thread, cp.async pipeline.
// u-space recurrence: u' = s*u + (xs_t - xs_{t+1}),  xs = d0*x,  u = d0*(h-x)
//   t = tanh(u);  s = sigmoid(2*(c0 + c1*t + c2*t^2)) = 1/(1 + 2^w),
//   w = b0 + b1*t + b2*t^2  (b = -2*log2(e)*c)
// Chain per step: TANH(52) -> 2xFFMA(8) -> EX2(16) -> FADD(4) -> RCP(16) -> FFMA(4)
// out = (xs_511 + s_511*u_511) / d0

#define SEQ     512
#define BLOCK   64
#define PITCH   36           // floats/thread in smem (16x36B stride -> conflict-free LDS.128)
#define NCHUNK  (SEQ / 16)   // 32
#define LOG2E   1.4426950408889634f

__device__ __forceinline__ float tanh_fast(float x) {
    float y;
    asm("tanh.approx.f32 %0, %1;" : "=f"(y) : "f"(x));
    return y;
}
__device__ __forceinline__ float ex2_fast(float x) {
    float y;
    asm("ex2.approx.f32 %0, %1;" : "=f"(y) : "f"(x));
    return y;
}
__device__ __forceinline__ float rcp_fast(float x) {
    float y;
    asm("rcp.approx.f32 %0, %1;" : "=f"(y) : "f"(x));
    return y;
}

__global__ void __launch_bounds__(BLOCK) rnn_scan_kernel(
    const float* __restrict__ X,
    const float* __restrict__ W1,
    const float* __restrict__ W2,
    const float* __restrict__ bias,
    const float* __restrict__ Wz,
    const float* __restrict__ Ws,
    float* __restrict__ out)
{
    __shared__ float sbuf[BLOCK * PITCH];

    const int lt = threadIdx.x;
    const int r  = blockIdx.x * BLOCK + lt;

    // ----- uniform scalar constants -----
    const float a1 = 1.0f / (1.0f + expf(W1[1] - W1[0]));
    const float a2 = 1.0f / (1.0f + expf(W2[1] - W2[0]));
    float d0 = a1 - a2;
    if (fabsf(d0) < 1e-20f) d0 = 1e-20f;      // u-space exactly linear in d0
    const float rec = 1.0f / d0;
    const float wz = Wz[0];
    const float ws = Ws[0];
    const float b  = bias[0];
    // y' = c0 + c1*t + c2*t^2 (halved logits); s = sigmoid(2*y') = 1/(1+2^w),
    // w = -2*log2e*y'
    const float c0 = 0.5f * (b + wz);
    const float c1 = 0.5f * ws;
    const float c2 = -wz;
    const float b0 = -2.0f * LOG2E * c0;
    const float b1 = -2.0f * LOG2E * c1;
    const float b2 = -2.0f * LOG2E * c2;

    // ----- cp.async pipeline (R7 skeleton) -----
    const float* row = X + (size_t)r * SEQ;
    float* my = sbuf + lt * PITCH;            // [0..15] = A, [16..31] = B

    uint32_t sb;
    {
        uint64_t tmp;
        asm("cvta.to.shared.u64 %0, %1;" : "=l"(tmp) : "l"(my));
        sb = (uint32_t)tmp;
    }

#define ISSUE(half, c) do {                                                  \
        _Pragma("unroll")                                                    \
        for (int j = 0; j < 4; ++j) {                                        \
            asm volatile("cp.async.cg.shared.global [%0], [%1], 16;"         \
                         :: "r"(sb + (unsigned)(((half) * 16 + j * 4) * 4)), \
                            "l"(row + (c) * 16 + j * 4) : "memory");         \
        }                                                                    \
        asm volatile("cp.async.commit_group;" ::: "memory");                 \
    } while (0)
#define WAIT1() asm volatile("cp.async.wait_group 1;" ::: "memory")
#define WAIT0() asm volatile("cp.async.wait_group 0;" ::: "memory")

    float uv = 0.0f;     // u state
    float xsprev;        // d0 * x_t (previous element, scaled)

    // one scan step consuming raw element XF (= x_{t+1})
#define STEP(XF) do {                                            \
        float xscur = d0 * (XF);                                 \
        float t  = tanh_fast(uv);                                \
        float w  = fmaf(fmaf(b2, t, b1), t, b0);                 \
        float z  = ex2_fast(w);                                  \
        float s  = rcp_fast(z + 1.0f);                           \
        uv = fmaf(s, uv, xsprev - xscur);                        \
        xsprev = xscur;                                          \
    } while (0)

#define PROC(half, E0) do {                                                 \
        _Pragma("unroll")                                                   \
        for (int q = 0; q < 4; ++q) {                                       \
            float4 v = *reinterpret_cast<const float4*>(my + (half) * 16 + q * 4); \
            if (q > 0 || (E0) <= 0) STEP(v.x);                              \
            if (q > 0 || (E0) <= 1) STEP(v.y);                              \
            if (q > 0 || (E0) <= 2) STEP(v.z);                              \
            STEP(v.w);                                                      \
        }                                                                   \
    } while (0)

    ISSUE(0, 0);
    ISSUE(1, 1);

    WAIT1();                       // chunk 0 resident
    xsprev = d0 * my[0];           // xs_0; uv = 0 seeds u_1 on first STEP
    PROC(0, 1);                    // consume x_1 .. x_15

    #pragma unroll 1
    for (int c = 2; c < NCHUNK; c += 2) {
        ISSUE(0, c);               // prefetch chunk c -> A
        WAIT1();                   // chunk c-1 (B) resident
        PROC(1, 0);
        ISSUE(1, c + 1);           // prefetch chunk c+1 -> B (max 31)
        WAIT1();                   // chunk c (A) resident
        PROC(0, 0);
    }

    WAIT0();
    PROC(1, 0);                    // chunk 31: consume .. x_511

    // final gate s_511 = G(u_511); out = (xs_511 + s*u) / d0
    {
        float t  = tanh_fast(uv);
        float w  = fmaf(fmaf(b2, t, b1), t, b0);
        float z  = ex2_fast(w);
        float s  = rcp_fast(z + 1.0f);
        out[r] = rec * fmaf(s, uv, xsprev);
    }
}

extern "C" void kernel_launch(void* const* d_in, const int* in_sizes, int n_in,
                              void* d_out, int out_size)
{
    const float* X    = (const float*)d_in[0];
    const float* W1   = (const float*)d_in[1];
    const float* W2   = (const float*)d_in[2];
    const float* bias = (const float*)d_in[3];
    const float* Wz   = (const float*)d_in[4];
    const float* Ws   = (const float*)d_in[5];
    float* out = (float*)d_out;

    const int batch = out_size;                    // 65536
    const int grid  = (batch + BLOCK - 1) / BLOCK; // 1024
    rnn_scan_kernel<<<grid, BLOCK>>>(X, W1, W2, bias, Wz, Ws, out);
}

// round 14
// speedup vs baseline: 1.2680x; 1.2680x over previous
#include <cuda_runtime.h>
#include <cstdint>

// MinArchitecture scan, 2 rows/thread, single-MUFU chain:
//   t = tanh(u)  [MUFU]
//   s = Q(t)     [runtime-fitted deg-16 poly, evaluated packed in fma.rn.f32x2]
//   u' = s*u + (xs_t - xs_{t+1})   (u-space; xs = d0*x)
// out = (xs_511 + s_511*u_511)/d0
// Q fits s(t) = 0.5 + 0.5*tanh(c0 + c1*t + c2*t^2) on t in [-1,1] (Chebyshev->monomial).

#define SEQ     512
#define BLOCK   64
#define IL      2
#define TPITCH  68          // floats/thread: 2 rows * 32 + 4 pad (16B-aligned, conflict-free)
#define NCHUNK  (SEQ / 16)  // 32
#define QDEG    16          // poly degree (17 coeffs)

typedef unsigned long long ull;

__device__ __forceinline__ float tanh_fast(float x) {
    float y;
    asm("tanh.approx.f32 %0, %1;" : "=f"(y) : "f"(x));
    return y;
}
__device__ __forceinline__ ull pk2(float lo, float hi) {
    ull r;
    asm("mov.b64 %0, {%1, %2};" : "=l"(r) : "f"(lo), "f"(hi));
    return r;
}
__device__ __forceinline__ void upk2(float& lo, float& hi, ull v) {
    asm("mov.b64 {%0, %1}, %2;" : "=f"(lo), "=f"(hi) : "l"(v));
}
__device__ __forceinline__ ull fma2(ull a, ull b, ull c) {
    ull r;
    asm("fma.rn.f32x2 %0, %1, %2, %3;" : "=l"(r) : "l"(a), "l"(b), "l"(c));
    return r;
}
__device__ __forceinline__ ull mul2(ull a, ull b) {
    ull r;
    asm("mul.rn.f32x2 %0, %1, %2;" : "=l"(r) : "l"(a), "l"(b));
    return r;
}

__global__ void __launch_bounds__(BLOCK) rnn_scan_kernel(
    const float* __restrict__ X,
    const float* __restrict__ W1,
    const float* __restrict__ W2,
    const float* __restrict__ bias,
    const float* __restrict__ Wz,
    const float* __restrict__ Ws,
    float* __restrict__ out)
{
    __shared__ float sbuf[BLOCK * TPITCH];   // cp.async pipeline buffers
    __shared__ float sf[64];                 // fit: node values
    __shared__ float sa[QDEG + 1];           // fit: Chebyshev coeffs
    __shared__ float sq[QDEG + 1];           // fit: monomial coeffs

    const int lt  = threadIdx.x;
    const int tid = blockIdx.x * BLOCK + lt;
    const size_t r0 = (size_t)tid * IL;

    // ----- uniform scalar constants -----
    const float a1 = 1.0f / (1.0f + expf(W1[1] - W1[0]));
    const float a2 = 1.0f / (1.0f + expf(W2[1] - W2[0]));
    float d0 = a1 - a2;
    if (fabsf(d0) < 1e-20f) d0 = 1e-20f;     // u-space exactly linear in d0
    const float rec = 1.0f / d0;
    const float wz = Wz[0];
    const float ws = Ws[0];
    const float b  = bias[0];
    const float c0 = 0.5f * (b + wz);
    const float c1 = 0.5f * ws;
    const float c2 = -wz;

    // ----- runtime fit: s(t) on t in [-1,1], Chebyshev nodes (accurate tanhf) -----
    {
        const float PI = 3.14159265358979323846f;
        // node values: t_j = cos(pi*(j+0.5)/64)
        float th = PI * ((float)lt + 0.5f) / 64.0f;
        float t  = cosf(th);
        float y  = c0 + (c1 + c2 * t) * t;
        sf[lt] = 0.5f + 0.5f * tanhf(y);
        __syncthreads();
        // Chebyshev coeffs a_k = (2/64) sum_j f_j cos(k*th_j)  (a_0 halved)
        if (lt <= QDEG) {
            float acc = 0.0f;
            for (int j = 0; j < 64; ++j) {
                float thj = PI * ((float)j + 0.5f) / 64.0f;
                acc += sf[j] * cosf((float)lt * thj);
            }
            sa[lt] = acc * ((lt == 0) ? (1.0f / 64.0f) : (2.0f / 64.0f));
        }
        __syncthreads();
        // Chebyshev -> monomial, shuffle-parallel over coefficient index (warp 0)
        if (lt < 32) {
            int lane = lt;
            float prev = (lane == 0) ? 1.0f : 0.0f;   // T0 coeffs
            float cur  = (lane == 1) ? 1.0f : 0.0f;   // T1 coeffs
            float m = sa[0] * prev + sa[1] * cur;
            #pragma unroll
            for (int k = 2; k <= QDEG; ++k) {
                float up = __shfl_up_sync(0xffffffffu, cur, 1);
                if (lane == 0) up = 0.0f;
                float nxt = 2.0f * up - prev;         // T_k = 2x*T_{k-1} - T_{k-2}
                prev = cur; cur = nxt;
                m = fmaf(sa[k], cur, m);
            }
            if (lane <= QDEG) sq[lane] = m;
        }
        __syncthreads();
    }

    // packed monomial coefficients in registers
    ull Qc[QDEG + 1];
    #pragma unroll
    for (int k = 0; k <= QDEG; ++k) {
        float q = sq[k];
        Qc[k] = pk2(q, q);
    }

    // ----- cp.async pipeline, 2 rows/thread (R12 layout) -----
    float* my = sbuf + lt * TPITCH;   // row0 [0..31], row1 [32..63]; A=[0..15], B=[16..31]
    uint32_t sb;
    {
        uint64_t tmp;
        asm("cvta.to.shared.u64 %0, %1;" : "=l"(tmp) : "l"(my));
        sb = (uint32_t)tmp;
    }
    const float* row0 = X + r0 * SEQ;
    const float* row1 = X + (r0 + 1) * SEQ;

#define ISSUE(half, c) do {                                                    \
        _Pragma("unroll")                                                      \
        for (int j = 0; j < 4; ++j) {                                          \
            asm volatile("cp.async.cg.shared.global [%0], [%1], 16;"           \
                :: "r"(sb + (unsigned)(((half) * 16 + j * 4) * 4)),            \
                   "l"(row0 + (c) * 16 + j * 4) : "memory");                   \
            asm volatile("cp.async.cg.shared.global [%0], [%1], 16;"           \
                :: "r"(sb + (unsigned)((32 + (half) * 16 + j * 4) * 4)),       \
                   "l"(row1 + (c) * 16 + j * 4) : "memory");                   \
        }                                                                      \
        asm volatile("cp.async.commit_group;" ::: "memory");                   \
    } while (0)
#define WAIT1() asm volatile("cp.async.wait_group 1;" ::: "memory")
#define WAIT0() asm volatile("cp.async.wait_group 0;" ::: "memory")

    float uv0 = 0.0f, uv1 = 0.0f;   // u state per row
    float xsp0, xsp1;               // d0 * x_t (previous), per row

    // gate for both rows: one tanh each (MUFU), shared packed poly
#define GATE(s0, s1) do {                                          \
        float t0 = tanh_fast(uv0);                                 \
        float t1 = tanh_fast(uv1);                                 \
        ull T   = pk2(t0, t1);                                     \
        ull T2  = mul2(T, T);                                      \
        ull T4  = mul2(T2, T2);                                    \
        ull T8  = mul2(T4, T4);                                    \
        ull T16 = mul2(T8, T8);                                    \
        ull p0 = fma2(Qc[1],  T, Qc[0]);                           \
        ull p1 = fma2(Qc[3],  T, Qc[2]);                           \
        ull p2 = fma2(Qc[5],  T, Qc[4]);                           \
        ull p3 = fma2(Qc[7],  T, Qc[6]);                           \
        ull p4 = fma2(Qc[9],  T, Qc[8]);                           \
        ull p5 = fma2(Qc[11], T, Qc[10]);                          \
        ull p6 = fma2(Qc[13], T, Qc[12]);                          \
        ull p7 = fma2(Qc[15], T, Qc[14]);                          \
        ull q0 = fma2(p1, T2, p0);                                 \
        ull q1 = fma2(p3, T2, p2);                                 \
        ull q2 = fma2(p5, T2, p4);                                 \
        ull q3 = fma2(p7, T2, p6);                                 \
        ull r0_ = fma2(q1, T4, q0);                                \
        ull r1_ = fma2(q3, T4, q2);                                \
        ull s_  = fma2(r1_, T8, r0_);                              \
        ull S   = fma2(Qc[16], T16, s_);                           \
        upk2(s0, s1, S);                                           \
    } while (0)

    // one step of both rows consuming elements XF0, XF1 (= x_{t+1})
#define STEP2(XF0, XF1) do {                                       \
        float xc0 = d0 * (XF0);                                    \
        float xc1 = d0 * (XF1);                                    \
        float s0, s1;                                              \
        GATE(s0, s1);                                              \
        uv0 = fmaf(s0, uv0, xsp0 - xc0);                           \
        uv1 = fmaf(s1, uv1, xsp1 - xc1);                           \
        xsp0 = xc0; xsp1 = xc1;                                    \
    } while (0)

#define PROC(half, E0) do {                                                    \
        _Pragma("unroll")                                                      \
        for (int q = 0; q < 4; ++q) {                                          \
            float4 v0 = *reinterpret_cast<const float4*>(my + (half) * 16 + q * 4);      \
            float4 v1 = *reinterpret_cast<const float4*>(my + 32 + (half) * 16 + q * 4); \
            if (q > 0 || (E0) <= 0) STEP2(v0.x, v1.x);                         \
            if (q > 0 || (E0) <= 1) STEP2(v0.y, v1.y);                         \
            if (q > 0 || (E0) <= 2) STEP2(v0.z, v1.z);                         \
            STEP2(v0.w, v1.w);                                                 \
        }                                                                      \
    } while (0)

    ISSUE(0, 0);
    ISSUE(1, 1);

    WAIT1();                        // chunk 0 resident
    xsp0 = d0 * my[0];              // xs_0 row0; uv=0 seeds u_1 on first STEP
    xsp1 = d0 * my[32];             // xs_0 row1
    PROC(0, 1);                     // consume x_1 .. x_15

    #pragma unroll 1
    for (int c = 2; c < NCHUNK; c += 2) {
        ISSUE(0, c);                // prefetch chunk c -> A
        WAIT1();                    // chunk c-1 (B) resident
        PROC(1, 0);
        ISSUE(1, c + 1);            // prefetch chunk c+1 -> B (max 31)
        WAIT1();                    // chunk c (A) resident
        PROC(0, 0);
    }

    WAIT0();
    PROC(1, 0);                     // chunk 31: consume .. x_511

    // final gates: out = (xs_511 + s_511*u_511)/d0
    {
        float s0, s1;
        GATE(s0, s1);
        float2 o;
        o.x = rec * fmaf(s0, uv0, xsp0);
        o.y = rec * fmaf(s1, uv1, xsp1);
        *reinterpret_cast<float2*>(out + r0) = o;
    }
}

extern "C" void kernel_launch(void* const* d_in, const int* in_sizes, int n_in,
                              void* d_out, int out_size)
{
    const float* X    = (const float*)d_in[0];
    const float* W1   = (const float*)d_in[1];
    const float* W2   = (const float*)d_in[2];
    const float* bias = (const float*)d_in[3];
    const float* Wz   = (const float*)d_in[4];
    const float* Ws   = (const float*)d_in[5];
    float* out = (float*)d_out;

    const int batch = out_size;                                 // 65536
    const int grid  = (batch + IL * BLOCK - 1) / (IL * BLOCK);  // 512
    rnn_scan_kernel<<<grid, BLOCK>>>(X, W1, W2, bias, Wz, Ws, out);
}

// round 15
// speedup vs baseline: 1.4961x; 1.1799x over previous
#include <cuda_runtime.h>
#include <cstdint>

// MinArchitecture scan, 1 row/thread, cp.async pipeline, u-space recurrence:
//   t = tanh(u)                      [1 MUFU]
//   s = P8(t)                        [runtime-fitted deg-8 Chebyshev poly, scalar FFMA]
//   u' = s*u + (xs_t - xs_{t+1})     [xs = d0*x]
// out = (xs_511 + s_511*u_511)/d0
// P8 fits s(t) = 0.5 + 0.5*tanh(c0 + c1*t + c2*t^2) on t in [-1,1].

#define SEQ     512
#define BLOCK   64
#define PITCH   36           // floats/thread in smem (16x36B stride -> conflict-free LDS.128)
#define NCHUNK  (SEQ / 16)   // 32
#define QDEG    8            // poly degree (9 coeffs)

__device__ __forceinline__ float tanh_fast(float x) {
    float y;
    asm("tanh.approx.f32 %0, %1;" : "=f"(y) : "f"(x));
    return y;
}

__global__ void __launch_bounds__(BLOCK) rnn_scan_kernel(
    const float* __restrict__ X,
    const float* __restrict__ W1,
    const float* __restrict__ W2,
    const float* __restrict__ bias,
    const float* __restrict__ Wz,
    const float* __restrict__ Ws,
    float* __restrict__ out)
{
    __shared__ float sbuf[BLOCK * PITCH];
    __shared__ float sf[64];             // fit scratch: node values
    __shared__ float sa[QDEG + 1];       // Chebyshev coeffs
    __shared__ float sq[QDEG + 1];       // monomial coeffs

    const int lt = threadIdx.x;
    const int r  = blockIdx.x * BLOCK + lt;

    // ----- uniform scalar constants -----
    const float a1 = 1.0f / (1.0f + expf(W1[1] - W1[0]));
    const float a2 = 1.0f / (1.0f + expf(W2[1] - W2[0]));
    float d0 = a1 - a2;
    if (fabsf(d0) < 1e-20f) d0 = 1e-20f;      // u-space exactly linear in d0
    const float rec = 1.0f / d0;
    const float wz = Wz[0];
    const float ws = Ws[0];
    const float b  = bias[0];
    const float c0 = 0.5f * (b + wz);
    const float c1 = 0.5f * ws;
    const float c2 = -wz;

    // ----- runtime Chebyshev fit of s(t) on [-1,1] (validated in R14) -----
    {
        const float PI = 3.14159265358979323846f;
        float th = PI * ((float)lt + 0.5f) / 64.0f;
        float t  = cosf(th);
        float y  = c0 + (c1 + c2 * t) * t;
        sf[lt] = 0.5f + 0.5f * tanhf(y);
        __syncthreads();
        if (lt <= QDEG) {
            float acc = 0.0f;
            for (int j = 0; j < 64; ++j) {
                float thj = PI * ((float)j + 0.5f) / 64.0f;
                acc += sf[j] * cosf((float)lt * thj);
            }
            sa[lt] = acc * ((lt == 0) ? (1.0f / 64.0f) : (2.0f / 64.0f));
        }
        __syncthreads();
        // Chebyshev -> monomial via shuffle-parallel T_k recurrence (warp 0)
        if (lt < 32) {
            int lane = lt;
            float prev = (lane == 0) ? 1.0f : 0.0f;   // T0
            float cur  = (lane == 1) ? 1.0f : 0.0f;   // T1
            float m = sa[0] * prev + sa[1] * cur;
            #pragma unroll
            for (int k = 2; k <= QDEG; ++k) {
                float up = __shfl_up_sync(0xffffffffu, cur, 1);
                if (lane == 0) up = 0.0f;
                float nxt = 2.0f * up - prev;
                prev = cur; cur = nxt;
                m = fmaf(sa[k], cur, m);
            }
            if (lane <= QDEG) sq[lane] = m;
        }
        __syncthreads();
    }

    const float q0 = sq[0], q1 = sq[1], q2 = sq[2], q3 = sq[3], q4 = sq[4],
                q5 = sq[5], q6 = sq[6], q7 = sq[7], q8 = sq[8];

    // ----- cp.async pipeline (R7 skeleton) -----
    const float* row = X + (size_t)r * SEQ;
    float* my = sbuf + lt * PITCH;            // [0..15] = A, [16..31] = B

    uint32_t sb;
    {
        uint64_t tmp;
        asm("cvta.to.shared.u64 %0, %1;" : "=l"(tmp) : "l"(my));
        sb = (uint32_t)tmp;
    }

#define ISSUE(half, c) do {                                                  \
        _Pragma("unroll")                                                    \
        for (int j = 0; j < 4; ++j) {                                        \
            asm volatile("cp.async.cg.shared.global [%0], [%1], 16;"         \
                         :: "r"(sb + (unsigned)(((half) * 16 + j * 4) * 4)), \
                            "l"(row + (c) * 16 + j * 4) : "memory");         \
        }                                                                    \
        asm volatile("cp.async.commit_group;" ::: "memory");                 \
    } while (0)
#define WAIT1() asm volatile("cp.async.wait_group 1;" ::: "memory")
#define WAIT0() asm volatile("cp.async.wait_group 0;" ::: "memory")

    float uv = 0.0f;     // u state
    float xsprev;        // d0 * x_t (previous element, scaled)

    // deg-8 Estrin gate; chain: tanh -> t2 -> t4 -> t8 -> S -> uv'
#define GATE(sv) do {                                          \
        float t  = tanh_fast(uv);                              \
        float t2 = t * t;                                      \
        float t4 = t2 * t2;                                    \
        float t8 = t4 * t4;                                    \
        float e0 = fmaf(q1, t, q0);                            \
        float e1 = fmaf(q3, t, q2);                            \
        float e2 = fmaf(q5, t, q4);                            \
        float e3 = fmaf(q7, t, q6);                            \
        float f0 = fmaf(e1, t2, e0);                           \
        float f1 = fmaf(e3, t2, e2);                           \
        float g  = fmaf(f1, t4, f0);                           \
        sv = fmaf(q8, t8, g);                                  \
    } while (0)

    // one scan step consuming raw element XF (= x_{t+1})
#define STEP(XF) do {                                          \
        float xscur = d0 * (XF);                               \
        float s;                                               \
        GATE(s);                                               \
        uv = fmaf(s, uv, xsprev - xscur);                      \
        xsprev = xscur;                                        \
    } while (0)

#define PROC(half, E0) do {                                                 \
        _Pragma("unroll")                                                   \
        for (int q = 0; q < 4; ++q) {                                       \
            float4 v = *reinterpret_cast<const float4*>(my + (half) * 16 + q * 4); \
            if (q > 0 || (E0) <= 0) STEP(v.x);                              \
            if (q > 0 || (E0) <= 1) STEP(v.y);                              \
            if (q > 0 || (E0) <= 2) STEP(v.z);                              \
            STEP(v.w);                                                      \
        }                                                                   \
    } while (0)

    ISSUE(0, 0);
    ISSUE(1, 1);

    WAIT1();                       // chunk 0 resident
    xsprev = d0 * my[0];           // xs_0; uv = 0 seeds u_1 on first STEP
    PROC(0, 1);                    // consume x_1 .. x_15

    #pragma unroll 1
    for (int c = 2; c < NCHUNK; c += 2) {
        ISSUE(0, c);               // prefetch chunk c -> A
        WAIT1();                   // chunk c-1 (B) resident
        PROC(1, 0);
        ISSUE(1, c + 1);           // prefetch chunk c+1 -> B (max 31)
        WAIT1();                   // chunk c (A) resident
        PROC(0, 0);
    }

    WAIT0();
    PROC(1, 0);                    // chunk 31: consume .. x_511

    // final gate: out = (xs_511 + s_511*u_511)/d0
    {
        float s;
        GATE(s);
        out[r] = rec * fmaf(s, uv, xsprev);
    }
}

extern "C" void kernel_launch(void* const* d_in, const int* in_sizes, int n_in,
                              void* d_out, int out_size)
{
    const float* X    = (const float*)d_in[0];
    const float* W1   = (const float*)d_in[1];
    const float* W2   = (const float*)d_in[2];
    const float* bias = (const float*)d_in[3];
    const float* Wz   = (const float*)d_in[4];
    const float* Ws   = (const float*)d_in[5];
    float* out = (float*)d_out;

    const int batch = out_size;                    // 65536
    const int grid  = (batch + BLOCK - 1) / BLOCK; // 1024
    rnn_scan_kernel<<<grid, BLOCK>>>(X, W1, W2, bias, Wz, Ws, out);
}